// round 2
// baseline (speedup 1.0000x reference)
#include <cuda_runtime.h>
#include <cuda_bf16.h>

// Net_33294586479043: 2-layer GCN ending in log_softmax over axis=1 of a
// [N, 1] tensor. log_softmax over a size-1 axis is exactly 0.0f for every
// element (stable formulation: 0 - log(exp(0)) = 0, no rounding). The whole
// GCN is dead code; the output is 100,000 exact zeros.
//
// This round: minimize kernel ramp time. out_size = 100000 floats = 25000
// float4 = 12500 float4-pairs. 49 blocks x 256 threads, each thread does two
// straight-line STG.128s (no grid-stride loop, no tail branch). Straggler
// guard handles any out_size not divisible by 8 defensively.

__global__ void __launch_bounds__(256, 1)
zero_out_kernel(float4* __restrict__ out4, int n4) {
    int i = (blockIdx.x * blockDim.x + threadIdx.x) * 2;
    const float4 z = make_float4(0.f, 0.f, 0.f, 0.f);
    if (i < n4)     out4[i]     = z;
    if (i + 1 < n4) out4[i + 1] = z;
}

__global__ void __launch_bounds__(64, 1)
zero_tail_kernel(float* __restrict__ out, int start, int n) {
    int i = start + threadIdx.x;
    if (i < n) out[i] = 0.0f;
}

extern "C" void kernel_launch(void* const* d_in, const int* in_sizes, int n_in,
                              void* d_out, int out_size) {
    (void)d_in; (void)in_sizes; (void)n_in;
    float* out = (float*)d_out;
    int n  = out_size;   // 100000 expected
    int n4 = n / 4;      // 25000 float4 (exact for expected size)

    // 2 float4 per thread
    int threads = 256;
    int blocks  = (n4 / 2 + threads - 1) / threads;   // 49 for n4=25000
    if (blocks < 1) blocks = 1;
    zero_out_kernel<<<blocks, threads>>>((float4*)out, n4);

    // Defensive tail (no-op for out_size % 4 == 0); only launch if needed.
    int tail_start = n4 * 4;
    if (tail_start < n) {
        zero_tail_kernel<<<1, 64>>>(out, tail_start, n);
    }
}

// round 3
// speedup vs baseline: 1.0491x; 1.0491x over previous
#include <cuda_runtime.h>
#include <cuda_bf16.h>

// Net_33294586479043: 2-layer GCN ending in log_softmax over axis=1 of a
// [N, 1] tensor. log_softmax over a size-1 axis is exactly 0.0f per element
// (0 - log(exp(0)) = 0, no rounding). The whole GCN is dead code; the
// reference output is 100,000 exact zeros.
//
// Launch-ramp-bound regime (measured: 400KB at 118 GB/s = nowhere near HBM
// bound; kernel dur ~= chip launch floor). Round-2 showed per-warp path
// matters more than block count: one STG.128 per thread, wide grid, no
// loops. 25000 float4 -> 98 blocks x 256 threads, each thread one
// predicated 16B store. Defensive scalar tail handled by the very last
// thread (compiled-in but predicated off for out_size % 4 == 0).

__global__ void __launch_bounds__(256, 1)
zero_out_kernel(float4* __restrict__ out4, int n4,
                float* __restrict__ out, int tail_start, int n) {
    int i = blockIdx.x * blockDim.x + threadIdx.x;
    if (i < n4) {
        out4[i] = make_float4(0.f, 0.f, 0.f, 0.f);
    }
    // defensive tail: only the single highest-indexed thread, and only if
    // out_size % 4 != 0 (never for the expected 100000).
    if (i == n4 && tail_start < n) {
        for (int t = tail_start; t < n; ++t) out[t] = 0.0f;
    }
}

extern "C" void kernel_launch(void* const* d_in, const int* in_sizes, int n_in,
                              void* d_out, int out_size) {
    (void)d_in; (void)in_sizes; (void)n_in;
    float* out = (float*)d_out;
    int n  = out_size;   // 100000 expected
    int n4 = n / 4;      // 25000 float4

    int threads = 256;
    int blocks  = (n4 + 1 + threads - 1) / threads;  // +1 covers tail thread; 98 for n=100000
    if (blocks < 1) blocks = 1;

    zero_out_kernel<<<blocks, threads>>>((float4*)out, n4, out, n4 * 4, n);
}